// round 4
// baseline (speedup 1.0000x reference)
#include <cuda_runtime.h>
#include <cstdint>
#include <cstddef>

#define V_N   50000
#define E_N   160000
#define APAD  132          // padded row stride (floats) for k-major smem tiles

typedef unsigned long long ull;

// Scratch: per pass p (8) and side s (A=0 src-half, B=1 dst-half): [V][128] f32.
// Index: ((p*2+s)*V + v)*128 + k   (== (by*V + v)*128 + k with by = 2p+s)
__device__ __align__(128) float g_tab[(size_t)16 * V_N * 128];

union F2 { ull u; float2 f; };

__device__ __forceinline__ ull pack_dup(float x) {
    unsigned u = __float_as_uint(x);
    ull r;
    asm("mov.b64 %0, {%1, %2};" : "=l"(r) : "r"(u), "r"(u));
    return r;
}

__device__ __forceinline__ void fma2(ull& c, ull a, ull b) {
    asm("fma.rn.f32x2 %0, %1, %2, %0;" : "+l"(c) : "l"(a), "l"(b));
}

// 128x128x128 register-blocked GEMM core, packed f32x2 FMAs.
// As: [128 k][APAD rows] (k-major, transposed), Bs: [128 k][128 cols].
// Thread computes rows r0..r0+7, cols c0..c0+7 as 8x4 f32x2 pairs.
__device__ __forceinline__ void gemm_core(const float* __restrict__ As,
                                          const float* __restrict__ Bs,
                                          int r0, int c0, ull acc[32]) {
#pragma unroll 4
    for (int k = 0; k < 128; ++k) {
        const float4 a0 = *reinterpret_cast<const float4*>(As + k * APAD + r0);
        const float4 a1 = *reinterpret_cast<const float4*>(As + k * APAD + r0 + 4);
        const ull* br = reinterpret_cast<const ull*>(Bs + k * 128 + c0);
        ull b0 = br[0], b1 = br[1], b2 = br[2], b3 = br[3];
        float av[8] = {a0.x, a0.y, a0.z, a0.w, a1.x, a1.y, a1.z, a1.w};
#pragma unroll
        for (int i = 0; i < 8; ++i) {
            ull ax = pack_dup(av[i]);
            fma2(acc[i * 4 + 0], ax, b0);
            fma2(acc[i * 4 + 1], ax, b1);
            fma2(acc[i * 4 + 2], ax, b2);
            fma2(acc[i * 4 + 3], ax, b3);
        }
    }
}

// ---------------------------------------------------------------------------
// Kernel 1: precompute tab = emb @ [W1 halves]  (V x 2048, K=128)
// grid = (ceil(V/128)=391, 16). by selects a contiguous 64KB block of W1:
// Wblk[k][jj] = W1[(by*128 + k)*128 + jj]  (verified: j0=by*128 => p=by>>1, s=by&1)
// ---------------------------------------------------------------------------
__global__ __launch_bounds__(256, 1)
void pre_kernel(const float* __restrict__ emb, const float* __restrict__ W1) {
    extern __shared__ float sm[];
    float* As = sm;                    // 128 x APAD
    float* Bs = sm + 128 * APAD;       // 128 x 128

    const int t  = threadIdx.x;
    const int v0 = blockIdx.x * 128;
    const int by = blockIdx.y;

    // Load emb tile transposed into As[k][v_local]. Lanes vary v_local =>
    // conflict-free STS (uncoalesced LDG is fine: emb is L2-resident).
#pragma unroll
    for (int i = 0; i < 16; ++i) {
        int idx = i * 256 + t;
        int v   = idx & 127;
        int kq  = idx >> 7;            // 0..31 (float4 groups)
        int vg  = v0 + v; if (vg >= V_N) vg = V_N - 1;
        float4 a = *reinterpret_cast<const float4*>(emb + (size_t)vg * 128 + kq * 4);
        int k = kq * 4;
        As[(k + 0) * APAD + v] = a.x;
        As[(k + 1) * APAD + v] = a.y;
        As[(k + 2) * APAD + v] = a.z;
        As[(k + 3) * APAD + v] = a.w;
    }

    // Load W1 block (already k-major, contiguous 64KB)
    const float4* wb = reinterpret_cast<const float4*>(W1 + (size_t)by * 16384);
    float4* b4 = reinterpret_cast<float4*>(Bs);
#pragma unroll
    for (int i = 0; i < 16; ++i) b4[i * 256 + t] = wb[i * 256 + t];
    __syncthreads();

    const int tx = t & 15, ty = t >> 4;
    const int r0 = ty * 8, c0 = tx * 8;
    ull acc[32];
#pragma unroll
    for (int i = 0; i < 32; ++i) acc[i] = 0ull;

    gemm_core(As, Bs, r0, c0, acc);

    float* base = g_tab + (size_t)by * V_N * 128;
#pragma unroll
    for (int i = 0; i < 8; ++i) {
        int v = v0 + r0 + i;
        if (v < V_N) {
            float2* crow = reinterpret_cast<float2*>(base + (size_t)v * 128 + c0);
#pragma unroll
            for (int j = 0; j < 4; ++j) { F2 u; u.u = acc[i * 4 + j]; crow[j] = u.f; }
        }
    }
}

// ---------------------------------------------------------------------------
// Kernel 2: per-edge phase for all 8 passes.
// grid = (E/128 = 1250, 8). For pass p: gather A[src]+B[dst], relu -> H,
// msg = H @ W2[p], atomic-scatter msg rows to out[adj[:,ep]].
// ---------------------------------------------------------------------------
__global__ __launch_bounds__(256, 1)
void edge_kernel(const float* __restrict__ W2,
                 const int* __restrict__ a0p, const int* __restrict__ a1p,
                 const int* __restrict__ a2p, const int* __restrict__ a3p,
                 float* __restrict__ out) {
    extern __shared__ float sm[];
    float* Hs = sm;                        // 128 x APAD (k-major)
    float* Ws = sm + 128 * APAD;           // 128 x 128
    int* ssm = reinterpret_cast<int*>(Ws + 128 * 128);
    int* dsm = ssm + 128;
    int* tsm = dsm + 128;

    const int t  = threadIdx.x;
    const int p  = blockIdx.y;             // pass 0..7
    const int l  = p >> 1, ep = p & 1;
    const int* adj = (l == 0) ? a0p : (l == 1) ? a1p : (l == 2) ? a2p : a3p;
    const int e0 = blockIdx.x * 128;

    if (t < 128) {
        int2 sd = reinterpret_cast<const int2*>(adj)[e0 + t];
        ssm[t] = sd.x;
        dsm[t] = sd.y;
        tsm[t] = ep ? sd.y : sd.x;
    }

    // W2 block for this pass (contiguous 64KB, k-major)
    const float4* wb = reinterpret_cast<const float4*>(W2 + (size_t)p * 16384);
    float4* w4 = reinterpret_cast<float4*>(Ws);
#pragma unroll
    for (int i = 0; i < 16; ++i) w4[i * 256 + t] = wb[i * 256 + t];
    __syncthreads();

    const float* Abase = g_tab + (size_t)(2 * p) * V_N * 128;
    const float* Bbase = Abase + (size_t)V_N * 128;

    // Gather + add + relu, stored transposed into Hs[k][e].
    // Lanes vary e => conflict-free STS.
#pragma unroll
    for (int i = 0; i < 16; ++i) {
        int idx = i * 256 + t;
        int e   = idx & 127;
        int kq  = idx >> 7;
        const float4 av = *reinterpret_cast<const float4*>(Abase + (size_t)ssm[e] * 128 + kq * 4);
        const float4 bv = *reinterpret_cast<const float4*>(Bbase + (size_t)dsm[e] * 128 + kq * 4);
        int k = kq * 4;
        Hs[(k + 0) * APAD + e] = fmaxf(av.x + bv.x, 0.0f);
        Hs[(k + 1) * APAD + e] = fmaxf(av.y + bv.y, 0.0f);
        Hs[(k + 2) * APAD + e] = fmaxf(av.z + bv.z, 0.0f);
        Hs[(k + 3) * APAD + e] = fmaxf(av.w + bv.w, 0.0f);
    }
    __syncthreads();

    const int tx = t & 15, ty = t >> 4;
    const int r0 = ty * 8, c0 = tx * 8;
    ull acc[32];
#pragma unroll
    for (int i = 0; i < 32; ++i) acc[i] = 0ull;

    gemm_core(Hs, Ws, r0, c0, acc);

    // Scatter: 128-bit vector atomics (RED.128), 16B-aligned (c0 multiple of 8).
#pragma unroll
    for (int i = 0; i < 8; ++i) {
        int e = r0 + i;
        float* orow = out + (size_t)tsm[e] * 128 + c0;
        F2 u0, u1, u2, u3;
        u0.u = acc[i * 4 + 0]; u1.u = acc[i * 4 + 1];
        u2.u = acc[i * 4 + 2]; u3.u = acc[i * 4 + 3];
        atomicAdd(reinterpret_cast<float4*>(orow),
                  make_float4(u0.f.x, u0.f.y, u1.f.x, u1.f.y));
        atomicAdd(reinterpret_cast<float4*>(orow + 4),
                  make_float4(u2.f.x, u2.f.y, u3.f.x, u3.f.y));
    }
}

__global__ void zero_kernel(float* out, int n) {
    int i = blockIdx.x * 256 + threadIdx.x;
    if (i < n) out[i] = 0.0f;
}

__global__ void relu_kernel(float* out, int n) {
    int i = blockIdx.x * 256 + threadIdx.x;
    if (i < n) out[i] = fmaxf(out[i], 0.0f);
}

extern "C" void kernel_launch(void* const* d_in, const int* in_sizes, int n_in,
                              void* d_out, int out_size) {
    const float* emb = (const float*)d_in[0];
    const int*   a0  = (const int*)d_in[1];
    const int*   a1  = (const int*)d_in[2];
    const int*   a2  = (const int*)d_in[3];
    const int*   a3  = (const int*)d_in[4];
    const float* W1  = (const float*)d_in[5];
    const float* W2  = (const float*)d_in[6];
    float* out = (float*)d_out;

    const int SMEM_P = (128 * APAD + 128 * 128) * 4;          // 133120 B
    const int SMEM_E = SMEM_P + 3 * 128 * 4;                  // 134656 B
    cudaFuncSetAttribute(pre_kernel,  cudaFuncAttributeMaxDynamicSharedMemorySize, SMEM_P);
    cudaFuncSetAttribute(edge_kernel, cudaFuncAttributeMaxDynamicSharedMemorySize, SMEM_E);

    const int n = out_size;
    zero_kernel<<<(n + 255) / 256, 256>>>(out, n);
    pre_kernel<<<dim3((V_N + 127) / 128, 16), 256, SMEM_P>>>(emb, W1);
    edge_kernel<<<dim3(E_N / 128, 8), 256, SMEM_E>>>(W2, a0, a1, a2, a3, out);
    relu_kernel<<<(n + 255) / 256, 256>>>(out, n);
}

// round 5
// speedup vs baseline: 1.4672x; 1.4672x over previous
#include <cuda_runtime.h>
#include <cstdint>
#include <cstddef>

#define V_N   50000
#define E_N   160000
#define APAD  260          // padded row stride (floats) for 256-wide k-major smem tiles

typedef unsigned long long ull;

// Scratch:
// g_tab: per pass p (8), side s (0=src-half of W1, 1=dst-half): [V][128] f32.
//        index ((2p+s)*V + v)*128 + k
// g_G:   per pass p: segment-summed relu'd hidden vectors [V][128] f32.
__device__ __align__(128) float g_tab[(size_t)16 * V_N * 128];
__device__ __align__(128) float g_G[(size_t)8 * V_N * 128];

union F2 { ull u; float2 f; };

__device__ __forceinline__ ull pack_dup(float x) {
    unsigned u = __float_as_uint(x);
    ull r;
    asm("mov.b64 %0, {%1, %2};" : "=l"(r) : "r"(u), "r"(u));
    return r;
}

__device__ __forceinline__ void fma2(ull& c, ull a, ull b) {
    asm("fma.rn.f32x2 %0, %1, %2, %0;" : "+l"(c) : "l"(a), "l"(b));
}

// 256x128x128 tile GEMM core, 512 threads, 8 rows x 8 cols per thread.
// As: [128 k][APAD rows] (k-major transposed), Bs: [128 k][128 cols].
// Accumulates into acc (does NOT reset) so callers can chain K-blocks.
__device__ __forceinline__ void gemm_core(const float* __restrict__ As,
                                          const float* __restrict__ Bs,
                                          int r0, int c0, ull acc[32]) {
#pragma unroll 4
    for (int k = 0; k < 128; ++k) {
        const float4 a0 = *reinterpret_cast<const float4*>(As + k * APAD + r0);
        const float4 a1 = *reinterpret_cast<const float4*>(As + k * APAD + r0 + 4);
        const ull* br = reinterpret_cast<const ull*>(Bs + k * 128 + c0);
        ull b0 = br[0], b1 = br[1], b2 = br[2], b3 = br[3];
        float av[8] = {a0.x, a0.y, a0.z, a0.w, a1.x, a1.y, a1.z, a1.w};
#pragma unroll
        for (int i = 0; i < 8; ++i) {
            ull ax = pack_dup(av[i]);
            fma2(acc[i * 4 + 0], ax, b0);
            fma2(acc[i * 4 + 1], ax, b1);
            fma2(acc[i * 4 + 2], ax, b2);
            fma2(acc[i * 4 + 3], ax, b3);
        }
    }
}

// ---------------------------------------------------------------------------
// Kernel 1: tab = emb @ [all 16 W1 half-blocks]   (V x 2048, K=128)
// grid = (ceil(V/256)=196, 16), block=512. by picks a contiguous 64KB W1 block
// (rows [by*128,(by+1)*128) of flattened (2048,128) W1) => by = 2p+s.
// ---------------------------------------------------------------------------
__global__ __launch_bounds__(512, 1)
void pre_kernel(const float* __restrict__ emb, const float* __restrict__ W1) {
    extern __shared__ float sm[];
    float* As = sm;                    // 128 x APAD
    float* Bs = sm + 128 * APAD;       // 128 x 128

    const int t  = threadIdx.x;
    const int v0 = blockIdx.x * 256;
    const int by = blockIdx.y;

    // emb tile transposed into As[k][v_local]; lanes vary v => conflict-free STS.
#pragma unroll
    for (int i = 0; i < 16; ++i) {
        int idx = i * 512 + t;
        int v   = idx & 255;
        int kq  = idx >> 8;            // 0..31 float4 groups along k
        int vg  = v0 + v; if (vg >= V_N) vg = V_N - 1;
        float4 a = *reinterpret_cast<const float4*>(emb + (size_t)vg * 128 + kq * 4);
        int k = kq * 4;
        As[(k + 0) * APAD + v] = a.x;
        As[(k + 1) * APAD + v] = a.y;
        As[(k + 2) * APAD + v] = a.z;
        As[(k + 3) * APAD + v] = a.w;
    }

    const float4* wb = reinterpret_cast<const float4*>(W1 + (size_t)by * 16384);
    float4* b4 = reinterpret_cast<float4*>(Bs);
#pragma unroll
    for (int i = 0; i < 8; ++i) b4[i * 512 + t] = wb[i * 512 + t];
    __syncthreads();

    const int tx = t & 15, ty = t >> 4;      // ty: 0..31
    const int r0 = ty * 8, c0 = tx * 8;
    ull acc[32];
#pragma unroll
    for (int i = 0; i < 32; ++i) acc[i] = 0ull;

    gemm_core(As, Bs, r0, c0, acc);

    float* base = g_tab + (size_t)by * V_N * 128;
#pragma unroll
    for (int i = 0; i < 8; ++i) {
        int v = v0 + r0 + i;
        if (v < V_N) {
            float4* crow = reinterpret_cast<float4*>(base + (size_t)v * 128 + c0);
            F2 u0, u1, u2, u3;
            u0.u = acc[i * 4 + 0]; u1.u = acc[i * 4 + 1];
            u2.u = acc[i * 4 + 2]; u3.u = acc[i * 4 + 3];
            crow[0] = make_float4(u0.f.x, u0.f.y, u1.f.x, u1.f.y);
            crow[1] = make_float4(u2.f.x, u2.f.y, u3.f.x, u3.f.y);
        }
    }
}

// ---------------------------------------------------------------------------
// Kernel 2: zero the G accumulators (8*V*128 floats).
// ---------------------------------------------------------------------------
__global__ void zero_G_kernel() {
    size_t i = (size_t)blockIdx.x * 256 + threadIdx.x;
    reinterpret_cast<float4*>(g_G)[i] = make_float4(0.f, 0.f, 0.f, 0.f);
}

// ---------------------------------------------------------------------------
// Kernel 3: edge phase — pure gather + add + relu + scatter (NO GEMM).
// For pass p, edge e: h = relu(A_p[src] + B_p[dst]); G_p[tgt] += h.
// 16 threads per edge, 32B (2 x float4) per thread. grid=(E/16, 8), block=256.
// ---------------------------------------------------------------------------
__global__ __launch_bounds__(256)
void edge_kernel(const int* __restrict__ a0p, const int* __restrict__ a1p,
                 const int* __restrict__ a2p, const int* __restrict__ a3p) {
    const int t    = threadIdx.x;
    const int p    = blockIdx.y;
    const int l    = p >> 1, ep = p & 1;
    const int* adj = (l == 0) ? a0p : (l == 1) ? a1p : (l == 2) ? a2p : a3p;

    const int e    = blockIdx.x * 16 + (t >> 4);
    const int half = t & 15;                      // 8 floats per thread

    int2 sd = reinterpret_cast<const int2*>(adj)[e];
    int tgt = ep ? sd.y : sd.x;

    const float* A = g_tab + (size_t)(2 * p) * V_N * 128;
    const float* B = A + (size_t)V_N * 128;

    const float4* ap = reinterpret_cast<const float4*>(A + (size_t)sd.x * 128 + half * 8);
    const float4* bp = reinterpret_cast<const float4*>(B + (size_t)sd.y * 128 + half * 8);
    float4 x0 = ap[0], x1 = ap[1];
    float4 y0 = bp[0], y1 = bp[1];

    float4 h0 = make_float4(fmaxf(x0.x + y0.x, 0.f), fmaxf(x0.y + y0.y, 0.f),
                            fmaxf(x0.z + y0.z, 0.f), fmaxf(x0.w + y0.w, 0.f));
    float4 h1 = make_float4(fmaxf(x1.x + y1.x, 0.f), fmaxf(x1.y + y1.y, 0.f),
                            fmaxf(x1.z + y1.z, 0.f), fmaxf(x1.w + y1.w, 0.f));

    float* g = g_G + ((size_t)p * V_N + tgt) * 128 + half * 8;
    atomicAdd(reinterpret_cast<float4*>(g), h0);
    atomicAdd(reinterpret_cast<float4*>(g + 4), h1);
}

// ---------------------------------------------------------------------------
// Kernel 4: out = relu( sum_p G_p @ W2_p )   (V x 128, K = 8*128)
// grid = 196, block = 512. Direct overwrite of out (no zero/atomics/epilogue).
// ---------------------------------------------------------------------------
__global__ __launch_bounds__(512, 1)
void out_kernel(const float* __restrict__ W2, float* __restrict__ out) {
    extern __shared__ float sm[];
    float* As = sm;                    // 128 x APAD
    float* Bs = sm + 128 * APAD;       // 128 x 128

    const int t  = threadIdx.x;
    const int v0 = blockIdx.x * 256;
    const int tx = t & 15, ty = t >> 4;
    const int r0 = ty * 8, c0 = tx * 8;

    ull acc[32];
#pragma unroll
    for (int i = 0; i < 32; ++i) acc[i] = 0ull;

    for (int p = 0; p < 8; ++p) {
        const float* Gp = g_G + (size_t)p * V_N * 128;
#pragma unroll
        for (int i = 0; i < 16; ++i) {
            int idx = i * 512 + t;
            int v   = idx & 255;
            int kq  = idx >> 8;
            int vg  = v0 + v; if (vg >= V_N) vg = V_N - 1;
            float4 a = *reinterpret_cast<const float4*>(Gp + (size_t)vg * 128 + kq * 4);
            int k = kq * 4;
            As[(k + 0) * APAD + v] = a.x;
            As[(k + 1) * APAD + v] = a.y;
            As[(k + 2) * APAD + v] = a.z;
            As[(k + 3) * APAD + v] = a.w;
        }
        const float4* wb = reinterpret_cast<const float4*>(W2 + (size_t)p * 16384);
        float4* b4 = reinterpret_cast<float4*>(Bs);
#pragma unroll
        for (int i = 0; i < 8; ++i) b4[i * 512 + t] = wb[i * 512 + t];
        __syncthreads();

        gemm_core(As, Bs, r0, c0, acc);
        __syncthreads();   // protect smem reuse by next p iteration
    }

#pragma unroll
    for (int i = 0; i < 8; ++i) {
        int v = v0 + r0 + i;
        if (v < V_N) {
            float4* crow = reinterpret_cast<float4*>(out + (size_t)v * 128 + c0);
            F2 u0, u1, u2, u3;
            u0.u = acc[i * 4 + 0]; u1.u = acc[i * 4 + 1];
            u2.u = acc[i * 4 + 2]; u3.u = acc[i * 4 + 3];
            crow[0] = make_float4(fmaxf(u0.f.x, 0.f), fmaxf(u0.f.y, 0.f),
                                  fmaxf(u1.f.x, 0.f), fmaxf(u1.f.y, 0.f));
            crow[1] = make_float4(fmaxf(u2.f.x, 0.f), fmaxf(u2.f.y, 0.f),
                                  fmaxf(u3.f.x, 0.f), fmaxf(u3.f.y, 0.f));
        }
    }
}

extern "C" void kernel_launch(void* const* d_in, const int* in_sizes, int n_in,
                              void* d_out, int out_size) {
    const float* emb = (const float*)d_in[0];
    const int*   a0  = (const int*)d_in[1];
    const int*   a1  = (const int*)d_in[2];
    const int*   a2  = (const int*)d_in[3];
    const int*   a3  = (const int*)d_in[4];
    const float* W1  = (const float*)d_in[5];
    const float* W2  = (const float*)d_in[6];
    float* out = (float*)d_out;

    const int SMEM = (128 * APAD + 128 * 128) * 4;   // 198656 B
    cudaFuncSetAttribute(pre_kernel, cudaFuncAttributeMaxDynamicSharedMemorySize, SMEM);
    cudaFuncSetAttribute(out_kernel, cudaFuncAttributeMaxDynamicSharedMemorySize, SMEM);

    const int VT = (V_N + 255) / 256;                // 196 row-tiles

    zero_G_kernel<<<(8 * V_N * 128 / 4) / 256, 256>>>();
    pre_kernel<<<dim3(VT, 16), 512, SMEM>>>(emb, W1);
    edge_kernel<<<dim3(E_N / 16, 8), 256>>>(a0, a1, a2, a3);
    out_kernel<<<VT, 512, SMEM>>>(W2, out);
}

// round 7
// speedup vs baseline: 2.6092x; 1.7784x over previous
#include <cuda_runtime.h>
#include <cuda_bf16.h>
#include <cstdint>
#include <cstddef>

#define V_N 50000
#define E_N 160000
#define SA  136                       // padded bf16 row stride (272 B)

typedef unsigned long long ull;
typedef unsigned int u32;

// ---------------------------------------------------------------------------
// Device scratch
// g_tab: per (pass p, side s): [V][128] f32, slab by = 2p+s (flat 128-row
//        block of W1).  g_G: per pass, segment-summed relu'd hidden vectors.
// g_wimg: 24 weight images (16 W1-blocks + 8 W2-blocks), each [128 n][SA k]
//         bf16, hi then lo (34816 B each, 69632 B per block).
// ---------------------------------------------------------------------------
__device__ __align__(128) float g_tab[(size_t)16 * V_N * 128];
__device__ __align__(128) float g_G[(size_t)8 * V_N * 128];
__device__ __align__(256) unsigned short g_wimg[(size_t)24 * 2 * 128 * SA];

#define WIMG_BLK (2 * 128 * SA)       // u16 elems per block (hi+lo)

// smem layout (bytes)
#define SM_A_HI 0
#define SM_A_LO 34816
#define SM_B_HI 69632
#define SM_B_LO 104448
#define SM_TOTAL 139264

// bf16x2 MMA: D(16x8,f32) += A(16x16,row) * B(16x8,col)
static __device__ __forceinline__ void mma16816(float d[4], const u32 a[4], const u32 b[2]) {
    asm volatile(
        "mma.sync.aligned.m16n8k16.row.col.f32.bf16.bf16.f32 "
        "{%0,%1,%2,%3}, {%4,%5,%6,%7}, {%8,%9}, {%0,%1,%2,%3};"
        : "+f"(d[0]), "+f"(d[1]), "+f"(d[2]), "+f"(d[3])
        : "r"(a[0]), "r"(a[1]), "r"(a[2]), "r"(a[3]), "r"(b[0]), "r"(b[1]));
}

// ---------------------------------------------------------------------------
// Split an f32 [128 rows][128 k] tile (row-major stride 128, rows clamped to
// V_N) into hi/lo bf16 smem tiles with stride SA. 256 threads: thread t does
// row t>>1, k-half (t&1)*64.
// ---------------------------------------------------------------------------
static __device__ __forceinline__ void load_A_tile(const float* __restrict__ base,
                                                   int v0, char* sm, int t) {
    const int row  = t >> 1;
    const int half = (t & 1) * 64;
    int vg = v0 + row; if (vg >= V_N) vg = V_N - 1;
    const float4* src = reinterpret_cast<const float4*>(base + (size_t)vg * 128 + half);
    char* hi = sm + SM_A_HI + (size_t)(row * SA + half) * 2;
    char* lo = sm + SM_A_LO + (size_t)(row * SA + half) * 2;
#pragma unroll
    for (int q = 0; q < 16; ++q) {
        float4 x = src[q];
        u32 u0 = __float_as_uint(x.x), u1 = __float_as_uint(x.y);
        u32 u2 = __float_as_uint(x.z), u3 = __float_as_uint(x.w);
        u32 h01 = __byte_perm(u0, u1, 0x7632);          // truncated bf16 pair
        u32 h23 = __byte_perm(u2, u3, 0x7632);
        float r0 = x.x - __uint_as_float(u0 & 0xFFFF0000u);
        float r1 = x.y - __uint_as_float(u1 & 0xFFFF0000u);
        float r2 = x.z - __uint_as_float(u2 & 0xFFFF0000u);
        float r3 = x.w - __uint_as_float(u3 & 0xFFFF0000u);
        u32 l01, l23;
        asm("cvt.rn.bf16x2.f32 %0, %1, %2;" : "=r"(l01) : "f"(r1), "f"(r0));
        asm("cvt.rn.bf16x2.f32 %0, %1, %2;" : "=r"(l23) : "f"(r3), "f"(r2));
        *reinterpret_cast<ull*>(hi + q * 8) = ((ull)h23 << 32) | h01;
        *reinterpret_cast<ull*>(lo + q * 8) = ((ull)l23 << 32) | l01;
    }
}

// ---------------------------------------------------------------------------
// 3-split 128x128x128 bf16 MMA over smem tiles, accumulating into d[16][4].
// 8 warps: warp tile 64m x 32n (wm = w>>2, wn = w&3); 4 m-tiles x 4 n-tiles.
// A/B fragment loads are plain LDS.32, conflict-free at stride SA=136.
// ---------------------------------------------------------------------------
static __device__ __forceinline__ void mma_block(const char* sm, int w, int lane,
                                                 float d[16][4]) {
    const int g  = lane >> 2;         // group id 0..7
    const int tg = lane & 3;          // thread-in-group
    const int m0 = (w >> 2) * 64;
    const int n0 = (w & 3) * 32;
    const char* Ah = sm + SM_A_HI;
    const char* Al = sm + SM_A_LO;
    const char* Bh = sm + SM_B_HI;
    const char* Bl = sm + SM_B_LO;

#pragma unroll
    for (int ks = 0; ks < 8; ++ks) {
        const int kb = ks * 16;
        u32 ah[4][4], al[4][4], bh[4][2], bl[4][2];
#pragma unroll
        for (int i = 0; i < 4; ++i) {
            int m = m0 + i * 16 + g;
            size_t o0 = (size_t)(m * SA + kb + 2 * tg) * 2;
            size_t o1 = (size_t)((m + 8) * SA + kb + 2 * tg) * 2;
            ah[i][0] = *reinterpret_cast<const u32*>(Ah + o0);
            ah[i][1] = *reinterpret_cast<const u32*>(Ah + o1);
            ah[i][2] = *reinterpret_cast<const u32*>(Ah + o0 + 16);
            ah[i][3] = *reinterpret_cast<const u32*>(Ah + o1 + 16);
            al[i][0] = *reinterpret_cast<const u32*>(Al + o0);
            al[i][1] = *reinterpret_cast<const u32*>(Al + o1);
            al[i][2] = *reinterpret_cast<const u32*>(Al + o0 + 16);
            al[i][3] = *reinterpret_cast<const u32*>(Al + o1 + 16);
        }
#pragma unroll
        for (int j = 0; j < 4; ++j) {
            int n = n0 + j * 8 + g;
            size_t o = (size_t)(n * SA + kb + 2 * tg) * 2;
            bh[j][0] = *reinterpret_cast<const u32*>(Bh + o);
            bh[j][1] = *reinterpret_cast<const u32*>(Bh + o + 16);
            bl[j][0] = *reinterpret_cast<const u32*>(Bl + o);
            bl[j][1] = *reinterpret_cast<const u32*>(Bl + o + 16);
        }
#pragma unroll
        for (int i = 0; i < 4; ++i)
#pragma unroll
            for (int j = 0; j < 4; ++j) {
                mma16816(d[i * 4 + j], ah[i], bh[j]);
                mma16816(d[i * 4 + j], ah[i], bl[j]);
                mma16816(d[i * 4 + j], al[i], bh[j]);
            }
    }
}

// ---------------------------------------------------------------------------
// Kernel: build weight images. blk 0..15 = W1 flat 128-row blocks (by=2p+s);
// 16..23 = W2[p]. Image[n][k] = W[k][n] (transposed), split hi/lo.
// ---------------------------------------------------------------------------
__global__ void w_prep_kernel(const float* __restrict__ W1, const float* __restrict__ W2) {
    const int blk = blockIdx.x;
    const float* src = (blk < 16) ? (W1 + (size_t)blk * 16384)
                                  : (W2 + (size_t)(blk - 16) * 16384);
    unsigned short* hi = g_wimg + (size_t)blk * WIMG_BLK;
    unsigned short* lo = hi + 128 * SA;
    for (int idx = threadIdx.x; idx < 16384; idx += blockDim.x) {
        int n = idx >> 7, k = idx & 127;
        float x = src[(size_t)k * 128 + n];
        u32 u = __float_as_uint(x);
        float r = x - __uint_as_float(u & 0xFFFF0000u);
        u32 lob;
        asm("cvt.rn.bf16x2.f32 %0, %1, %2;" : "=r"(lob) : "f"(0.0f), "f"(r));
        hi[n * SA + k] = (unsigned short)(u >> 16);
        lo[n * SA + k] = (unsigned short)(lob & 0xFFFF);
    }
}

// ---------------------------------------------------------------------------
// Kernel: tab[by] = emb @ W1blk[by] for all 16 by.  grid=391, block=256.
// ---------------------------------------------------------------------------
__global__ __launch_bounds__(256, 1)
void pre_mma(const float* __restrict__ emb) {
    extern __shared__ char sm[];
    const int t = threadIdx.x, w = t >> 5, lane = t & 31;
    const int v0 = blockIdx.x * 128;
    const int g = lane >> 2, tg = lane & 3;
    const int m0 = (w >> 2) * 64, n0 = (w & 3) * 32;

    load_A_tile(emb, v0, sm, t);

    for (int by = 0; by < 16; ++by) {
        // copy 69632B hi+lo weight image (B_LO contiguous after B_HI)
        const float4* wsrc = reinterpret_cast<const float4*>(g_wimg + (size_t)by * WIMG_BLK);
        float4* wdst = reinterpret_cast<float4*>(sm + SM_B_HI);
#pragma unroll
        for (int i = 0; i < 17; ++i) wdst[i * 256 + t] = wsrc[i * 256 + t];
        __syncthreads();

        float d[16][4];
#pragma unroll
        for (int i = 0; i < 16; ++i) { d[i][0] = d[i][1] = d[i][2] = d[i][3] = 0.f; }

        mma_block(sm, w, lane, d);

        // epilogue: D -> g_tab[by]
        float* base = g_tab + (size_t)by * V_N * 128;
#pragma unroll
        for (int i = 0; i < 4; ++i) {
            int vA = v0 + m0 + i * 16 + g;
            int vB = vA + 8;
#pragma unroll
            for (int j = 0; j < 4; ++j) {
                int col = n0 + j * 8 + 2 * tg;
                if (vA < V_N)
                    *reinterpret_cast<float2*>(base + (size_t)vA * 128 + col) =
                        make_float2(d[i * 4 + j][0], d[i * 4 + j][1]);
                if (vB < V_N)
                    *reinterpret_cast<float2*>(base + (size_t)vB * 128 + col) =
                        make_float2(d[i * 4 + j][2], d[i * 4 + j][3]);
            }
        }
        __syncthreads();   // all warps done with B smem before next by copy
    }
}

// ---------------------------------------------------------------------------
// Kernel: zero the G accumulators.
// ---------------------------------------------------------------------------
__global__ void zero_G_kernel() {
    size_t i = (size_t)blockIdx.x * 256 + threadIdx.x;
    reinterpret_cast<float4*>(g_G)[i] = make_float4(0.f, 0.f, 0.f, 0.f);
}

// ---------------------------------------------------------------------------
// Kernel: edge phase — gather + add + relu + vector-atomic scatter (as R4).
// ---------------------------------------------------------------------------
__global__ __launch_bounds__(256)
void edge_kernel(const int* __restrict__ a0p, const int* __restrict__ a1p,
                 const int* __restrict__ a2p, const int* __restrict__ a3p) {
    const int t    = threadIdx.x;
    const int p    = blockIdx.y;
    const int l    = p >> 1, ep = p & 1;
    const int* adj = (l == 0) ? a0p : (l == 1) ? a1p : (l == 2) ? a2p : a3p;

    const int e    = blockIdx.x * 16 + (t >> 4);
    const int half = t & 15;

    int2 sd = reinterpret_cast<const int2*>(adj)[e];
    int tgt = ep ? sd.y : sd.x;

    const float* A = g_tab + (size_t)(2 * p) * V_N * 128;
    const float* B = A + (size_t)V_N * 128;

    const float4* ap = reinterpret_cast<const float4*>(A + (size_t)sd.x * 128 + half * 8);
    const float4* bp = reinterpret_cast<const float4*>(B + (size_t)sd.y * 128 + half * 8);
    float4 x0 = ap[0], x1 = ap[1];
    float4 y0 = bp[0], y1 = bp[1];

    float4 h0 = make_float4(fmaxf(x0.x + y0.x, 0.f), fmaxf(x0.y + y0.y, 0.f),
                            fmaxf(x0.z + y0.z, 0.f), fmaxf(x0.w + y0.w, 0.f));
    float4 h1 = make_float4(fmaxf(x1.x + y1.x, 0.f), fmaxf(x1.y + y1.y, 0.f),
                            fmaxf(x1.z + y1.z, 0.f), fmaxf(x1.w + y1.w, 0.f));

    float* gq = g_G + ((size_t)p * V_N + tgt) * 128 + half * 8;
    atomicAdd(reinterpret_cast<float4*>(gq), h0);
    atomicAdd(reinterpret_cast<float4*>(gq + 4), h1);
}

// ---------------------------------------------------------------------------
// Kernel: out = relu( sum_p G_p @ W2_p ), K=1024 accumulated in registers.
// grid=391, block=256.
// ---------------------------------------------------------------------------
__global__ __launch_bounds__(256, 1)
void out_mma(float* __restrict__ out) {
    extern __shared__ char sm[];
    const int t = threadIdx.x, w = t >> 5, lane = t & 31;
    const int v0 = blockIdx.x * 128;
    const int g = lane >> 2, tg = lane & 3;
    const int m0 = (w >> 2) * 64, n0 = (w & 3) * 32;

    float d[16][4];
#pragma unroll
    for (int i = 0; i < 16; ++i) { d[i][0] = d[i][1] = d[i][2] = d[i][3] = 0.f; }

    for (int p = 0; p < 8; ++p) {
        load_A_tile(g_G + (size_t)p * V_N * 128, v0, sm, t);
        const float4* wsrc = reinterpret_cast<const float4*>(g_wimg + (size_t)(16 + p) * WIMG_BLK);
        float4* wdst = reinterpret_cast<float4*>(sm + SM_B_HI);
#pragma unroll
        for (int i = 0; i < 17; ++i) wdst[i * 256 + t] = wsrc[i * 256 + t];
        __syncthreads();

        mma_block(sm, w, lane, d);
        __syncthreads();   // smem (A and B) reused next p
    }

#pragma unroll
    for (int i = 0; i < 4; ++i) {
        int vA = v0 + m0 + i * 16 + g;
        int vB = vA + 8;
#pragma unroll
        for (int j = 0; j < 4; ++j) {
            int col = n0 + j * 8 + 2 * tg;
            if (vA < V_N)
                *reinterpret_cast<float2*>(out + (size_t)vA * 128 + col) =
                    make_float2(fmaxf(d[i * 4 + j][0], 0.f), fmaxf(d[i * 4 + j][1], 0.f));
            if (vB < V_N)
                *reinterpret_cast<float2*>(out + (size_t)vB * 128 + col) =
                    make_float2(fmaxf(d[i * 4 + j][2], 0.f), fmaxf(d[i * 4 + j][3], 0.f));
        }
    }
}

// ---------------------------------------------------------------------------
extern "C" void kernel_launch(void* const* d_in, const int* in_sizes, int n_in,
                              void* d_out, int out_size) {
    const float* emb = (const float*)d_in[0];
    const int*   a0  = (const int*)d_in[1];
    const int*   a1  = (const int*)d_in[2];
    const int*   a2  = (const int*)d_in[3];
    const int*   a3  = (const int*)d_in[4];
    const float* W1  = (const float*)d_in[5];
    const float* W2  = (const float*)d_in[6];
    float* out = (float*)d_out;

    cudaFuncSetAttribute(pre_mma, cudaFuncAttributeMaxDynamicSharedMemorySize, SM_TOTAL);
    cudaFuncSetAttribute(out_mma, cudaFuncAttributeMaxDynamicSharedMemorySize, SM_TOTAL);

    const int VT = (V_N + 127) / 128;   // 391 row-tiles

    zero_G_kernel<<<(8 * (size_t)V_N * 128 / 4) / 256, 256>>>();
    w_prep_kernel<<<24, 256>>>(W1, W2);
    pre_mma<<<VT, 256, SM_TOTAL>>>(emb);
    edge_kernel<<<dim3(E_N / 16, 8), 256>>>(a0, a1, a2, a3);
    out_mma<<<VT, 256, SM_TOTAL>>>(out);
}

// round 10
// speedup vs baseline: 2.7128x; 1.0397x over previous
#include <cuda_runtime.h>
#include <cuda_fp16.h>
#include <cstdint>
#include <cstddef>

#define V_N 50000
#define E_N 160000
#define SA  136                       // padded bf16/fp16 row stride (272 B)

typedef unsigned long long ull;
typedef unsigned int u32;

// ---------------------------------------------------------------------------
// Device scratch
// g_tab: per (pass p, side s): [V][128] fp16, slab by = 2p+s (flat 128-row
//        block of W1).  g_G: per pass, segment-summed relu'd hidden (f32).
// g_wimg: 24 weight images (16 W1 + 8 W2), each [128 n][SA k] bf16,
//         hi then lo (34816 B each, 69632 B per block).
// ---------------------------------------------------------------------------
__device__ __align__(128) __half g_tab[(size_t)16 * V_N * 128];
__device__ __align__(128) float  g_G[(size_t)8 * V_N * 128];
__device__ __align__(256) unsigned short g_wimg[(size_t)24 * 2 * 128 * SA];

#define WIMG_BLK   (2 * 128 * SA)     // u16 elems per block (hi+lo)
#define WIMG_BYTES (WIMG_BLK * 2)     // 69632 B

// smem layout (bytes): A hi/lo + two B buffers (hi+lo each)
#define SM_A_HI  0
#define SM_A_LO  34816
#define SM_B0    69632
#define SM_B1    139264
#define SM_TOTAL 208896

// ---------------------------------------------------------------------------
// cp.async helpers (sm_80 PTX, safe for compute_103 target)
// ---------------------------------------------------------------------------
static __device__ __forceinline__ u32 smem_u32(const void* p) {
    u32 a;
    asm("{ .reg .u64 t; cvta.to.shared.u64 t, %1; cvt.u32.u64 %0, t; }"
        : "=r"(a) : "l"(p));
    return a;
}
#define CP_ASYNC16(dst_u32, src_ptr) \
    asm volatile("cp.async.ca.shared.global [%0], [%1], 16;" \
                 :: "r"(dst_u32), "l"(src_ptr) : "memory")
#define CP_COMMIT()  asm volatile("cp.async.commit_group;" ::: "memory")
#define CP_WAIT(n)   asm volatile("cp.async.wait_group %0;" :: "n"(n) : "memory")

// bf16x2 MMA: D(16x8,f32) += A(16x16,row) * B(16x8,col)
static __device__ __forceinline__ void mma16816(float d[4], const u32 a[4], const u32 b[2]) {
    asm volatile(
        "mma.sync.aligned.m16n8k16.row.col.f32.bf16.bf16.f32 "
        "{%0,%1,%2,%3}, {%4,%5,%6,%7}, {%8,%9}, {%0,%1,%2,%3};"
        : "+f"(d[0]), "+f"(d[1]), "+f"(d[2]), "+f"(d[3])
        : "r"(a[0]), "r"(a[1]), "r"(a[2]), "r"(a[3]), "r"(b[0]), "r"(b[1]));
}

// ---------------------------------------------------------------------------
// Split an f32 [128 rows][128 k] tile (row-major stride 128, rows clamped)
// into bf16 hi/lo smem tiles with stride SA. 256 threads.
// ---------------------------------------------------------------------------
static __device__ __forceinline__ void load_A_tile(const float* __restrict__ base,
                                                   int v0, char* sm, int t) {
    const int row  = t >> 1;
    const int half = (t & 1) * 64;
    int vg = v0 + row; if (vg >= V_N) vg = V_N - 1;
    const float4* src = reinterpret_cast<const float4*>(base + (size_t)vg * 128 + half);
    char* hi = sm + SM_A_HI + (size_t)(row * SA + half) * 2;
    char* lo = sm + SM_A_LO + (size_t)(row * SA + half) * 2;
#pragma unroll
    for (int q = 0; q < 16; ++q) {
        float4 x = src[q];
        u32 u0 = __float_as_uint(x.x), u1 = __float_as_uint(x.y);
        u32 u2 = __float_as_uint(x.z), u3 = __float_as_uint(x.w);
        u32 h01 = __byte_perm(u0, u1, 0x7632);          // truncated bf16 pair
        u32 h23 = __byte_perm(u2, u3, 0x7632);
        float r0 = x.x - __uint_as_float(u0 & 0xFFFF0000u);
        float r1 = x.y - __uint_as_float(u1 & 0xFFFF0000u);
        float r2 = x.z - __uint_as_float(u2 & 0xFFFF0000u);
        float r3 = x.w - __uint_as_float(u3 & 0xFFFF0000u);
        u32 l01, l23;
        asm("cvt.rn.bf16x2.f32 %0, %1, %2;" : "=r"(l01) : "f"(r1), "f"(r0));
        asm("cvt.rn.bf16x2.f32 %0, %1, %2;" : "=r"(l23) : "f"(r3), "f"(r2));
        *reinterpret_cast<ull*>(hi + q * 8) = ((ull)h23 << 32) | h01;
        *reinterpret_cast<ull*>(lo + q * 8) = ((ull)l23 << 32) | l01;
    }
}

// ---------------------------------------------------------------------------
// 3-split 128x128x128 bf16 MMA over smem tiles, accumulating into d[16][4].
// 8 warps: warp tile 64m x 32n. Plain LDS.32, conflict-free at SA=136.
// Bbuf points at this iteration's weight image (hi at +0, lo at +34816).
// ---------------------------------------------------------------------------
static __device__ __forceinline__ void mma_block(const char* sm, const char* Bbuf,
                                                 int w, int lane, float d[16][4]) {
    const int g  = lane >> 2;
    const int tg = lane & 3;
    const int m0 = (w >> 2) * 64;
    const int n0 = (w & 3) * 32;
    const char* Ah = sm + SM_A_HI;
    const char* Al = sm + SM_A_LO;
    const char* Bh = Bbuf;
    const char* Bl = Bbuf + 34816;

#pragma unroll
    for (int ks = 0; ks < 8; ++ks) {
        const int kb = ks * 16;
        u32 ah[4][4], al[4][4], bh[4][2], bl[4][2];
#pragma unroll
        for (int i = 0; i < 4; ++i) {
            int m = m0 + i * 16 + g;
            size_t o0 = (size_t)(m * SA + kb + 2 * tg) * 2;
            size_t o1 = (size_t)((m + 8) * SA + kb + 2 * tg) * 2;
            ah[i][0] = *reinterpret_cast<const u32*>(Ah + o0);
            ah[i][1] = *reinterpret_cast<const u32*>(Ah + o1);
            ah[i][2] = *reinterpret_cast<const u32*>(Ah + o0 + 16);
            ah[i][3] = *reinterpret_cast<const u32*>(Ah + o1 + 16);
            al[i][0] = *reinterpret_cast<const u32*>(Al + o0);
            al[i][1] = *reinterpret_cast<const u32*>(Al + o1);
            al[i][2] = *reinterpret_cast<const u32*>(Al + o0 + 16);
            al[i][3] = *reinterpret_cast<const u32*>(Al + o1 + 16);
        }
#pragma unroll
        for (int j = 0; j < 4; ++j) {
            int n = n0 + j * 8 + g;
            size_t o = (size_t)(n * SA + kb + 2 * tg) * 2;
            bh[j][0] = *reinterpret_cast<const u32*>(Bh + o);
            bh[j][1] = *reinterpret_cast<const u32*>(Bh + o + 16);
            bl[j][0] = *reinterpret_cast<const u32*>(Bl + o);
            bl[j][1] = *reinterpret_cast<const u32*>(Bl + o + 16);
        }
#pragma unroll
        for (int i = 0; i < 4; ++i)
#pragma unroll
            for (int j = 0; j < 4; ++j) {
                mma16816(d[i * 4 + j], ah[i], bh[j]);
                mma16816(d[i * 4 + j], ah[i], bl[j]);
                mma16816(d[i * 4 + j], al[i], bh[j]);
            }
    }
}

// Issue one weight-image prefetch (17 x 16B per thread) + commit.
static __device__ __forceinline__ void prefetch_W(u32 dst_sb, const char* src, int t) {
#pragma unroll
    for (int i = 0; i < 17; ++i)
        CP_ASYNC16(dst_sb + (u32)(i * 4096 + t * 16), src + i * 4096 + t * 16);
    CP_COMMIT();
}

// ---------------------------------------------------------------------------
// Kernel: build weight images (blocks 0..23) + zero g_G (blocks 24..).
// blk 0..15 = W1 flat 128-row blocks (by=2p+s); 16..23 = W2[p].
// Image[n][k] = W[k][n] (transposed), split hi/lo.
// ---------------------------------------------------------------------------
#define ZERO_BLOCKS 2000
__global__ void w_prep_kernel(const float* __restrict__ W1, const float* __restrict__ W2) {
    const int blk = blockIdx.x;
    if (blk < 24) {
        const float* src = (blk < 16) ? (W1 + (size_t)blk * 16384)
                                      : (W2 + (size_t)(blk - 16) * 16384);
        unsigned short* hi = g_wimg + (size_t)blk * WIMG_BLK;
        unsigned short* lo = hi + 128 * SA;
        for (int idx = threadIdx.x; idx < 16384; idx += blockDim.x) {
            int n = idx >> 7, k = idx & 127;
            float x = src[(size_t)k * 128 + n];
            u32 u = __float_as_uint(x);
            float r = x - __uint_as_float(u & 0xFFFF0000u);
            u32 lob;
            asm("cvt.rn.bf16x2.f32 %0, %1, %2;" : "=r"(lob) : "f"(0.0f), "f"(r));
            hi[n * SA + k] = (unsigned short)(u >> 16);
            lo[n * SA + k] = (unsigned short)(lob & 0xFFFF);
        }
    } else {
        // zero g_G: 12.8M float4 across ZERO_BLOCKS*256 threads, 25 each
        const int i = (blk - 24) * 256 + threadIdx.x;
        float4* g4 = reinterpret_cast<float4*>(g_G);
#pragma unroll
        for (int c = 0; c < 25; ++c)
            g4[(size_t)i + (size_t)c * (ZERO_BLOCKS * 256)] = make_float4(0.f, 0.f, 0.f, 0.f);
    }
}

// ---------------------------------------------------------------------------
// Kernel: tab[by] = emb @ W1blk[by] for all 16 by (fp16 output).
// grid=391, block=256. Weight images double-buffered via cp.async.
// ---------------------------------------------------------------------------
__global__ __launch_bounds__(256, 1)
void pre_mma(const float* __restrict__ emb) {
    extern __shared__ char sm[];
    u32 sb = smem_u32(sm);
    const int t = threadIdx.x, w = t >> 5, lane = t & 31;
    const int v0 = blockIdx.x * 128;
    const int g = lane >> 2, tg = lane & 3;
    const int m0 = (w >> 2) * 64, n0 = (w & 3) * 32;
    const char* wbase = reinterpret_cast<const char*>(g_wimg);

    prefetch_W(sb + SM_B0, wbase, t);
    load_A_tile(emb, v0, sm, t);

    for (int by = 0; by < 16; ++by) {
        const u32 cur = (by & 1) ? SM_B1 : SM_B0;
        const u32 nxt = (by & 1) ? SM_B0 : SM_B1;
        if (by + 1 < 16) {
            prefetch_W(sb + nxt, wbase + (size_t)(by + 1) * WIMG_BYTES, t);
            CP_WAIT(1);
        } else {
            CP_WAIT(0);
        }
        __syncthreads();

        float d[16][4];
#pragma unroll
        for (int i = 0; i < 16; ++i) { d[i][0] = d[i][1] = d[i][2] = d[i][3] = 0.f; }

        mma_block(sm, sm + cur, w, lane, d);

        // epilogue: D -> g_tab[by] (fp16)
        __half* base = g_tab + (size_t)by * V_N * 128;
#pragma unroll
        for (int i = 0; i < 4; ++i) {
            int vA = v0 + m0 + i * 16 + g;
            int vB = vA + 8;
#pragma unroll
            for (int j = 0; j < 4; ++j) {
                int col = n0 + j * 8 + 2 * tg;
                if (vA < V_N)
                    *reinterpret_cast<__half2*>(base + (size_t)vA * 128 + col) =
                        __floats2half2_rn(d[i * 4 + j][0], d[i * 4 + j][1]);
                if (vB < V_N)
                    *reinterpret_cast<__half2*>(base + (size_t)vB * 128 + col) =
                        __floats2half2_rn(d[i * 4 + j][2], d[i * 4 + j][3]);
            }
        }
        __syncthreads();   // all warps done with cur before it becomes prefetch dst
    }
}

// ---------------------------------------------------------------------------
// Kernel: edge phase — fp16 gather + add + relu + f32 vector-atomic scatter.
// 16 threads/edge, 8 elems (16B fp16) per thread. grid=(E/16, 8), block=256.
// ---------------------------------------------------------------------------
__global__ __launch_bounds__(256)
void edge_kernel(const int* __restrict__ a0p, const int* __restrict__ a1p,
                 const int* __restrict__ a2p, const int* __restrict__ a3p) {
    const int t    = threadIdx.x;
    const int p    = blockIdx.y;
    const int l    = p >> 1, ep = p & 1;
    const int* adj = (l == 0) ? a0p : (l == 1) ? a1p : (l == 2) ? a2p : a3p;

    const int e    = blockIdx.x * 16 + (t >> 4);
    const int half = t & 15;                      // 8 halfs per thread

    int2 sd = reinterpret_cast<const int2*>(adj)[e];
    int tgt = ep ? sd.y : sd.x;

    const __half* A = g_tab + (size_t)(2 * p) * V_N * 128;
    const __half* B = A + (size_t)V_N * 128;

    uint4 av = *reinterpret_cast<const uint4*>(A + (size_t)sd.x * 128 + half * 8);
    uint4 bv = *reinterpret_cast<const uint4*>(B + (size_t)sd.y * 128 + half * 8);

    float2 a0 = __half22float2(*reinterpret_cast<__half2*>(&av.x));
    float2 a1 = __half22float2(*reinterpret_cast<__half2*>(&av.y));
    float2 a2 = __half22float2(*reinterpret_cast<__half2*>(&av.z));
    float2 a3 = __half22float2(*reinterpret_cast<__half2*>(&av.w));
    float2 b0 = __half22float2(*reinterpret_cast<__half2*>(&bv.x));
    float2 b1 = __half22float2(*reinterpret_cast<__half2*>(&bv.y));
    float2 b2 = __half22float2(*reinterpret_cast<__half2*>(&bv.z));
    float2 b3 = __half22float2(*reinterpret_cast<__half2*>(&bv.w));

    float4 h0 = make_float4(fmaxf(a0.x + b0.x, 0.f), fmaxf(a0.y + b0.y, 0.f),
                            fmaxf(a1.x + b1.x, 0.f), fmaxf(a1.y + b1.y, 0.f));
    float4 h1 = make_float4(fmaxf(a2.x + b2.x, 0.f), fmaxf(a2.y + b2.y, 0.f),
                            fmaxf(a3.x + b3.x, 0.f), fmaxf(a3.y + b3.y, 0.f));

    float* gq = g_G + ((size_t)p * V_N + tgt) * 128 + half * 8;
    atomicAdd(reinterpret_cast<float4*>(gq), h0);
    atomicAdd(reinterpret_cast<float4*>(gq + 4), h1);
}

// ---------------------------------------------------------------------------
// Kernel: out = relu( sum_p G_p @ W2_p ), K=1024 in registers.
// grid=391, block=256. Weights double-buffered via cp.async.
// ---------------------------------------------------------------------------
__global__ __launch_bounds__(256, 1)
void out_mma(float* __restrict__ out) {
    extern __shared__ char sm[];
    u32 sb = smem_u32(sm);
    const int t = threadIdx.x, w = t >> 5, lane = t & 31;
    const int v0 = blockIdx.x * 128;
    const int g = lane >> 2, tg = lane & 3;
    const int m0 = (w >> 2) * 64, n0 = (w & 3) * 32;
    const char* wbase = reinterpret_cast<const char*>(g_wimg) + (size_t)16 * WIMG_BYTES;

    prefetch_W(sb + SM_B0, wbase, t);

    float d[16][4];
#pragma unroll
    for (int i = 0; i < 16; ++i) { d[i][0] = d[i][1] = d[i][2] = d[i][3] = 0.f; }

    for (int p = 0; p < 8; ++p) {
        const u32 cur = (p & 1) ? SM_B1 : SM_B0;
        const u32 nxt = (p & 1) ? SM_B0 : SM_B1;
        load_A_tile(g_G + (size_t)p * V_N * 128, v0, sm, t);
        if (p + 1 < 8) {
            prefetch_W(sb + nxt, wbase + (size_t)(p + 1) * WIMG_BYTES, t);
            CP_WAIT(1);
        } else {
            CP_WAIT(0);
        }
        __syncthreads();

        mma_block(sm, sm + cur, w, lane, d);
        __syncthreads();   // A smem + cur buffer reused next p
    }

#pragma unroll
    for (int i = 0; i < 4; ++i) {
        int vA = v0 + m0 + i * 16 + g;
        int vB = vA + 8;
#pragma unroll
        for (int j = 0; j < 4; ++j) {
            int col = n0 + j * 8 + 2 * tg;
            if (vA < V_N)
                *reinterpret_cast<float2*>(out + (size_t)vA * 128 + col) =
                    make_float2(fmaxf(d[i * 4 + j][0], 0.f), fmaxf(d[i * 4 + j][1], 0.f));
            if (vB < V_N)
                *reinterpret_cast<float2*>(out + (size_t)vB * 128 + col) =
                    make_float2(fmaxf(d[i * 4 + j][2], 0.f), fmaxf(d[i * 4 + j][3], 0.f));
        }
    }
}

// ---------------------------------------------------------------------------
extern "C" void kernel_launch(void* const* d_in, const int* in_sizes, int n_in,
                              void* d_out, int out_size) {
    const float* emb = (const float*)d_in[0];
    const int*   a0  = (const int*)d_in[1];
    const int*   a1  = (const int*)d_in[2];
    const int*   a2  = (const int*)d_in[3];
    const int*   a3  = (const int*)d_in[4];
    const float* W1  = (const float*)d_in[5];
    const float* W2  = (const float*)d_in[6];
    float* out = (float*)d_out;

    cudaFuncSetAttribute(pre_mma, cudaFuncAttributeMaxDynamicSharedMemorySize, SM_TOTAL);
    cudaFuncSetAttribute(out_mma, cudaFuncAttributeMaxDynamicSharedMemorySize, SM_TOTAL);

    const int VT = (V_N + 127) / 128;   // 391 row-tiles

    w_prep_kernel<<<24 + ZERO_BLOCKS, 256>>>(W1, W2);
    pre_mma<<<VT, 256, SM_TOTAL>>>(emb);
    edge_kernel<<<dim3(E_N / 16, 8), 256>>>(a0, a1, a2, a3);
    out_mma<<<VT, 256, SM_TOTAL>>>(out);
}